// round 11
// baseline (speedup 1.0000x reference)
#include <cuda_runtime.h>
#include <cuda_bf16.h>

// MLLoss: per-sample hinge loss over [B,16] f32 distances -> scalar mean.
// Labels int32. At the path-independent memory ceiling (~6.34 TB/s; LDG
// strided/coalesced/predicated and TMA all converge). Traffic is minimal.
//
// R11 = R10 + DYNAMIC WORK STEALING: global ticket hands out 1024-row
// chunks so fast SMs absorb the CTA-finish spread (B300 spr_max@oe8 can be
// 1.3-2x with front-batched LDG). One ATOMG per chunk (~4K total).
// Last-block finalization also resets the ticket for graph replay.

#define THREADS    256
#define BLOCKS     1216       // 8 blocks/SM x 152 SMs = one full wave
#define CHUNK_ROWS 1024       // 4 inner iterations of THREADS rows

__device__ float        g_partial;   // zero at load; reset by last block each call
__device__ unsigned int g_count;
__device__ unsigned int g_next;      // work-stealing ticket

__device__ __forceinline__ float4 ldcs_256(const float4* p) {
    float4 v;
    asm("ld.global.cs.L2::256B.v4.f32 {%0,%1,%2,%3}, [%4];"
        : "=f"(v.x), "=f"(v.y), "=f"(v.z), "=f"(v.w) : "l"(p));
    return v;
}

__global__ __launch_bounds__(THREADS, 8)
void mlloss_kernel(const float4* __restrict__ dist4,  // [B,16] as B*4 float4
                   const int* __restrict__ doctor,    // [B] int32 {0,1,2}
                   const int* __restrict__ real_l,    // [B] int32 {0,1}
                   float* __restrict__ out,
                   int B, float inv_B)
{
    __shared__ unsigned int s_chunk;
    __shared__ float warp_sums[THREADS / 32];

    const int tid  = threadIdx.x;
    const int lane = tid & 31;
    const int wid  = tid >> 5;
    const unsigned int nchunks = ((unsigned)B + CHUNK_ROWS - 1) / CHUNK_ROWS;

    float acc = 0.0f;

    for (;;) {
        if (tid == 0) s_chunk = atomicAdd(&g_next, 1u);
        __syncthreads();
        const unsigned int c = s_chunk;
        __syncthreads();                      // s_chunk consumed before next write
        if (c >= nchunks) break;

        const int base_row = (int)(c * CHUNK_ROWS);
        #pragma unroll
        for (int i = 0; i < CHUNK_ROWS / THREADS; i++) {
            const int row = base_row + i * THREADS + tid;
            if (row >= B) break;

            const size_t base = (size_t)row * 4;
            const float4 a = ldcs_256(&dist4[base + 0]);
            const float4 b = ldcs_256(&dist4[base + 1]);
            const float4 cc = ldcs_256(&dist4[base + 2]);
            const float4 d = ldcs_256(&dist4[base + 3]);
            const int   dl = __ldcs(&doctor[row]);
            const int   rl = __ldcs(&real_l[row]);

            const float h0 = fmaxf(1.0f - a.x, 0.0f);
            const float h1 = fmaxf(1.0f - a.y, 0.0f);
            float hs = h0 + h1
                     + fmaxf(1.0f - a.z, 0.0f)  + fmaxf(1.0f - a.w, 0.0f)
                     + fmaxf(1.0f - b.x, 0.0f)  + fmaxf(1.0f - b.y, 0.0f)
                     + fmaxf(1.0f - b.z, 0.0f)  + fmaxf(1.0f - b.w, 0.0f)
                     + fmaxf(1.0f - cc.x, 0.0f) + fmaxf(1.0f - cc.y, 0.0f)
                     + fmaxf(1.0f - cc.z, 0.0f) + fmaxf(1.0f - cc.w, 0.0f)
                     + fmaxf(1.0f - d.x, 0.0f)  + fmaxf(1.0f - d.y, 0.0f)
                     + fmaxf(1.0f - d.z, 0.0f)  + fmaxf(1.0f - d.w, 0.0f);

            acc += (dl == 0) ? (a.x + hs - h0)
                 : (dl == 1) ? (a.y + hs - h1)
                             : ((rl == 0) ? h1 : h0);
        }
    }

    // warp reduce
    #pragma unroll
    for (int off = 16; off > 0; off >>= 1)
        acc += __shfl_xor_sync(0xFFFFFFFFu, acc, off);
    if (lane == 0) warp_sums[wid] = acc;
    __syncthreads();

    if (wid == 0) {
        float v = (lane < THREADS / 32) ? warp_sums[lane] : 0.0f;
        #pragma unroll
        for (int off = 16; off > 0; off >>= 1)
            v += __shfl_xor_sync(0xFFFFFFFFu, v, off);

        if (lane == 0) {
            atomicAdd(&g_partial, v);
            __threadfence();
            const unsigned int ticket = atomicAdd(&g_count, 1u);
            if (ticket == gridDim.x - 1) {
                const float total = atomicAdd(&g_partial, 0.0f); // fenced read
                out[0] = total * inv_B;
                g_partial = 0.0f;
                g_count   = 0u;
                g_next    = 0u;               // reset ticket for next replay
                __threadfence();
            }
        }
    }
}

extern "C" void kernel_launch(void* const* d_in, const int* in_sizes, int n_in,
                              void* d_out, int out_size)
{
    const float4* dist4  = (const float4*)d_in[0];
    const int*    doctor = (const int*)d_in[1];
    const int*    real_l = (const int*)d_in[2];
    float*        out    = (float*)d_out;

    const int B = in_sizes[1];
    const float inv_B = 1.0f / (float)B;

    mlloss_kernel<<<BLOCKS, THREADS>>>(dist4, doctor, real_l, out, B, inv_B);
}

// round 12
// speedup vs baseline: 1.0735x; 1.0735x over previous
#include <cuda_runtime.h>
#include <cuda_bf16.h>

// MLLoss: per-sample hinge loss over [B,16] f32 distances -> scalar mean.
// Labels int32.
//
// FINAL (R12) = R10, the measured-fastest kernel (48.16us, 6341 GB/s), with
// label loads hoisted ahead of distance loads. Evidence across R2-R11:
//  - all access paths (strided/coalesced/predicated LDG, TMA) cap at
//    6.0-6.34 TB/s -> path-independent memory ceiling
//  - traffic is irreducible (305 MB counted ~= logical footprint; 64B DRAM
//    granularity defeats sector-skipping)
//  - work stealing / coalescing / shuffle schemes all cost more than they save
// 305 MB / 6.34 TB/s = 48.1 us = this kernel. This is the floor.

#define THREADS 256
#define BLOCKS  1216   // 8 blocks/SM x 152 SMs = one full wave

__device__ float        g_partial;   // zero at load; reset by last block each call
__device__ unsigned int g_count;

__device__ __forceinline__ float4 ldcs_256(const float4* p) {
    float4 v;
    asm("ld.global.cs.L2::256B.v4.f32 {%0,%1,%2,%3}, [%4];"
        : "=f"(v.x), "=f"(v.y), "=f"(v.z), "=f"(v.w) : "l"(p));
    return v;
}

__global__ __launch_bounds__(THREADS, 8)
void mlloss_kernel(const float4* __restrict__ dist4,  // [B,16] as B*4 float4
                   const int* __restrict__ doctor,    // [B] int32 {0,1,2}
                   const int* __restrict__ real_l,    // [B] int32 {0,1}
                   float* __restrict__ out,
                   int B, float inv_B)
{
    const int tid    = blockIdx.x * blockDim.x + threadIdx.x;
    const int stride = gridDim.x * blockDim.x;

    float acc = 0.0f;

    for (int row = tid; row < B; row += stride) {
        // labels first: oldest in scoreboard, ready before the final select
        const int dl = __ldcs(&doctor[row]);
        const int rl = __ldcs(&real_l[row]);

        const size_t base = (size_t)row * 4;
        const float4 a = ldcs_256(&dist4[base + 0]);
        const float4 b = ldcs_256(&dist4[base + 1]);
        const float4 c = ldcs_256(&dist4[base + 2]);
        const float4 d = ldcs_256(&dist4[base + 3]);

        const float h0 = fmaxf(1.0f - a.x, 0.0f);
        const float h1 = fmaxf(1.0f - a.y, 0.0f);
        float hs = h0 + h1
                 + fmaxf(1.0f - a.z, 0.0f) + fmaxf(1.0f - a.w, 0.0f)
                 + fmaxf(1.0f - b.x, 0.0f) + fmaxf(1.0f - b.y, 0.0f)
                 + fmaxf(1.0f - b.z, 0.0f) + fmaxf(1.0f - b.w, 0.0f)
                 + fmaxf(1.0f - c.x, 0.0f) + fmaxf(1.0f - c.y, 0.0f)
                 + fmaxf(1.0f - c.z, 0.0f) + fmaxf(1.0f - c.w, 0.0f)
                 + fmaxf(1.0f - d.x, 0.0f) + fmaxf(1.0f - d.y, 0.0f)
                 + fmaxf(1.0f - d.z, 0.0f) + fmaxf(1.0f - d.w, 0.0f);

        const float loss = (dl == 0) ? (a.x + hs - h0)
                         : (dl == 1) ? (a.y + hs - h1)
                                     : ((rl == 0) ? h1 : h0);
        acc += loss;
    }

    // warp reduce
    #pragma unroll
    for (int off = 16; off > 0; off >>= 1)
        acc += __shfl_xor_sync(0xFFFFFFFFu, acc, off);

    __shared__ float warp_sums[THREADS / 32];
    const int lane = threadIdx.x & 31;
    const int wid  = threadIdx.x >> 5;
    if (lane == 0) warp_sums[wid] = acc;
    __syncthreads();

    if (wid == 0) {
        float v = (lane < THREADS / 32) ? warp_sums[lane] : 0.0f;
        #pragma unroll
        for (int off = 16; off > 0; off >>= 1)
            v += __shfl_xor_sync(0xFFFFFFFFu, v, off);

        if (lane == 0) {
            atomicAdd(&g_partial, v);
            __threadfence();
            const unsigned int ticket = atomicAdd(&g_count, 1u);
            if (ticket == gridDim.x - 1) {
                const float total = atomicAdd(&g_partial, 0.0f); // fenced read
                out[0] = total * inv_B;
                g_partial = 0.0f;
                g_count   = 0u;
                __threadfence();
            }
        }
    }
}

extern "C" void kernel_launch(void* const* d_in, const int* in_sizes, int n_in,
                              void* d_out, int out_size)
{
    const float4* dist4  = (const float4*)d_in[0];
    const int*    doctor = (const int*)d_in[1];
    const int*    real_l = (const int*)d_in[2];
    float*        out    = (float*)d_out;

    const int B = in_sizes[1];
    const float inv_B = 1.0f / (float)B;

    mlloss_kernel<<<BLOCKS, THREADS>>>(dist4, doctor, real_l, out, B, inv_B);
}